// round 1
// baseline (speedup 1.0000x reference)
#include <cuda_runtime.h>
#include <math.h>

// ImageNormalization2D: 61x61 box local contrast normalization, NHWC (16,1024,1024,2) fp32.
//
// Two fused kernels, each doing horizontal box (block prefix scan) + vertical box
// (per-thread sliding accumulator updated with row differences; leaving row re-read
// hits L2). Intermediate 'out' lives in a static __device__ scratch (no allocation).

#define NIMG 16
#define HH   1024
#define WW   1024
#define RAD  30
#define FS   61                 // filter size
#define TW   256                // output strip width (pixels)
#define LC   (TW + 2 * RAD)     // 316 row-buffer width
#define T1   320                // threads per block (>= LC, mult of 32)
#define NW   (T1 / 32)          // 10 warps
#define NSEG 4
#define SEG  (HH / NSEG)        // 256 output rows per block
#define INV_D (1.0f / 7442.0f)  // 1 / (61*61*2)  -- denom includes C per reference
#define EPS  1e-7f

// 128 MB scratch for 'out' intermediate (allocation-free per harness rules).
__device__ float2 g_mid[(size_t)NIMG * HH * WW];

__device__ __forceinline__ void wscan2(float2& v, int lane) {
#pragma unroll
    for (int off = 1; off < 32; off <<= 1) {
        float ax = __shfl_up_sync(0xffffffffu, v.x, off);
        float ay = __shfl_up_sync(0xffffffffu, v.y, off);
        if (lane >= off) { v.x += ax; v.y += ay; }
    }
}

__device__ __forceinline__ void wscan4(float2& a, float2& b, int lane) {
#pragma unroll
    for (int off = 1; off < 32; off <<= 1) {
        float ax = __shfl_up_sync(0xffffffffu, a.x, off);
        float ay = __shfl_up_sync(0xffffffffu, a.y, off);
        float bx = __shfl_up_sync(0xffffffffu, b.x, off);
        float by = __shfl_up_sync(0xffffffffu, b.y, off);
        if (lane >= off) { a.x += ax; a.y += ay; b.x += bx; b.y += by; }
    }
}

// ---------------------------------------------------------------------------
// Stage 1: out = x - box61x61(x) / 7442
// ---------------------------------------------------------------------------
__global__ __launch_bounds__(T1, 1)
void stage1_kernel(const float2* __restrict__ X)
{
    __shared__ float2 sP[2][T1];
    __shared__ float2 sWS[2][NW];
    __shared__ float2 sWO[2][NW];

    const int strip = blockIdx.x;
    const int seg   = blockIdx.y;
    const int n     = blockIdx.z;
    const int gx0   = strip * TW;
    const int ys0   = seg * SEG;
    const int t     = threadIdx.x;
    const int lane  = t & 31;
    const int w     = t >> 5;

    const int  gx  = gx0 - RAD + t;
    const bool xok = (t < LC) && (gx >= 0) && (gx < WW);

    const float2* __restrict__ img = X + (size_t)n * HH * WW;
    float2*       __restrict__ mid = g_mid + (size_t)n * HH * WW;

    float2 vacc = make_float2(0.f, 0.f);
    int buf = 0;

    const int NIT = FS + SEG;   // 61 priming + SEG emitting iterations
    for (int it = 0; it < NIT; ++it) {
        int enter, leave, yc; bool emit;
        if (it < FS) {          // prime vacc with rows [ys0-31, ys0+29]
            enter = ys0 - RAD - 1 + it; leave = -1; emit = false; yc = -1;
        } else {                // sliding: add row yc+30, drop row yc-31
            yc = ys0 + (it - FS); enter = yc + RAD; leave = yc - RAD - 1; emit = true;
        }
        if (!emit && enter < 0) continue;   // uniform skip (zero padding)

        // difference row (zero outside image)
        float2 v = make_float2(0.f, 0.f);
        if (xok) {
            if ((unsigned)enter < HH) v = img[enter * WW + gx];
            if ((unsigned)leave < HH) {
                float2 b = img[leave * WW + gx];
                v.x -= b.x; v.y -= b.y;
            }
        }

        // block-wide inclusive prefix scan of the difference row
        wscan2(v, lane);
        sP[buf][t] = v;
        if (lane == 31) sWS[buf][w] = v;
        __syncthreads();
        if (w == 0) {
            float2 s = (lane < NW) ? sWS[buf][lane] : make_float2(0.f, 0.f);
            float2 incl = s; wscan2(incl, lane);
            if (lane < NW) sWO[buf][lane] = make_float2(incl.x - s.x, incl.y - s.y);
        }
        __syncthreads();

        if (t < TW) {
            const int hi = t + 2 * RAD;
            float2 Ph = sP[buf][hi], Oh = sWO[buf][hi >> 5];
            float hx = Ph.x + Oh.x, hy = Ph.y + Oh.y;
            if (t > 0) {
                const int lo = t - 1;
                float2 Pl = sP[buf][lo], Ol = sWO[buf][lo >> 5];
                hx -= Pl.x + Ol.x; hy -= Pl.y + Ol.y;
            }
            vacc.x += hx; vacc.y += hy;
            if (emit) {
                float2 xc = img[yc * WW + (gx0 + t)];   // L2 hit (read 30 rows ago)
                float2 o  = make_float2(xc.x - vacc.x * INV_D,
                                        xc.y - vacc.y * INV_D);
                mid[yc * WW + (gx0 + t)] = o;
            }
        }
        buf ^= 1;
    }
}

// ---------------------------------------------------------------------------
// Stage 2: m = box(out)/D, q = box(out^2)/D, res = out / (sqrt(q - m^2) + eps)
// ---------------------------------------------------------------------------
__global__ __launch_bounds__(T1, 1)
void stage2_kernel(float2* __restrict__ OUT)
{
    __shared__ float2 sPa[2][T1];
    __shared__ float2 sPb[2][T1];
    __shared__ float2 sWSa[2][NW];
    __shared__ float2 sWSb[2][NW];
    __shared__ float2 sWOa[2][NW];
    __shared__ float2 sWOb[2][NW];

    const int strip = blockIdx.x;
    const int seg   = blockIdx.y;
    const int n     = blockIdx.z;
    const int gx0   = strip * TW;
    const int ys0   = seg * SEG;
    const int t     = threadIdx.x;
    const int lane  = t & 31;
    const int w     = t >> 5;

    const int  gx  = gx0 - RAD + t;
    const bool xok = (t < LC) && (gx >= 0) && (gx < WW);

    const float2* __restrict__ mid = g_mid + (size_t)n * HH * WW;
    float2*       __restrict__ res = OUT + (size_t)n * HH * WW;

    float2 va = make_float2(0.f, 0.f);   // sum of out
    float2 vb = make_float2(0.f, 0.f);   // sum of out^2
    int buf = 0;

    const int NIT = FS + SEG;
    for (int it = 0; it < NIT; ++it) {
        int enter, leave, yc; bool emit;
        if (it < FS) {
            enter = ys0 - RAD - 1 + it; leave = -1; emit = false; yc = -1;
        } else {
            yc = ys0 + (it - FS); enter = yc + RAD; leave = yc - RAD - 1; emit = true;
        }
        if (!emit && enter < 0) continue;

        float2 d  = make_float2(0.f, 0.f);
        float2 d2 = make_float2(0.f, 0.f);
        if (xok) {
            if ((unsigned)enter < HH) {
                float2 e = mid[enter * WW + gx];
                d = e; d2 = make_float2(e.x * e.x, e.y * e.y);
            }
            if ((unsigned)leave < HH) {
                float2 l = mid[leave * WW + gx];   // L2 hit (read 61 rows ago)
                d.x  -= l.x;        d.y  -= l.y;
                d2.x -= l.x * l.x;  d2.y -= l.y * l.y;
            }
        }

        wscan4(d, d2, lane);
        sPa[buf][t] = d;
        sPb[buf][t] = d2;
        if (lane == 31) { sWSa[buf][w] = d; sWSb[buf][w] = d2; }
        __syncthreads();
        if (w == 0) {
            float2 sa = (lane < NW) ? sWSa[buf][lane] : make_float2(0.f, 0.f);
            float2 sb = (lane < NW) ? sWSb[buf][lane] : make_float2(0.f, 0.f);
            float2 ia = sa, ib = sb; wscan4(ia, ib, lane);
            if (lane < NW) {
                sWOa[buf][lane] = make_float2(ia.x - sa.x, ia.y - sa.y);
                sWOb[buf][lane] = make_float2(ib.x - sb.x, ib.y - sb.y);
            }
        }
        __syncthreads();

        if (t < TW) {
            const int hi = t + 2 * RAD;
            float2 Pah = sPa[buf][hi], Oah = sWOa[buf][hi >> 5];
            float2 Pbh = sPb[buf][hi], Obh = sWOb[buf][hi >> 5];
            float hax = Pah.x + Oah.x, hay = Pah.y + Oah.y;
            float hbx = Pbh.x + Obh.x, hby = Pbh.y + Obh.y;
            if (t > 0) {
                const int lo = t - 1;
                float2 Pal = sPa[buf][lo], Oal = sWOa[buf][lo >> 5];
                float2 Pbl = sPb[buf][lo], Obl = sWOb[buf][lo >> 5];
                hax -= Pal.x + Oal.x; hay -= Pal.y + Oal.y;
                hbx -= Pbl.x + Obl.x; hby -= Pbl.y + Obl.y;
            }
            va.x += hax; va.y += hay;
            vb.x += hbx; vb.y += hby;
            if (emit) {
                float2 o  = mid[yc * WW + (gx0 + t)];   // L2 hit
                float mx = va.x * INV_D, my = va.y * INV_D;
                float qx = vb.x * INV_D, qy = vb.y * INV_D;
                float sx = sqrtf(fmaxf(qx - mx * mx, 0.f)) + EPS;
                float sy = sqrtf(fmaxf(qy - my * my, 0.f)) + EPS;
                res[yc * WW + (gx0 + t)] =
                    make_float2(__fdividef(o.x, sx), __fdividef(o.y, sy));
            }
        }
        buf ^= 1;
    }
}

extern "C" void kernel_launch(void* const* d_in, const int* in_sizes, int n_in,
                              void* d_out, int out_size)
{
    (void)in_sizes; (void)n_in; (void)out_size;
    const float2* x   = (const float2*)d_in[0];
    float2*       out = (float2*)d_out;

    dim3 grid(WW / TW, NSEG, NIMG);   // 4 strips x 4 segments x 16 images = 256 blocks
    stage1_kernel<<<grid, T1>>>(x);
    stage2_kernel<<<grid, T1>>>(out);
}

// round 2
// speedup vs baseline: 1.2429x; 1.2429x over previous
#include <cuda_runtime.h>
#include <math.h>

// 61x61 box local-contrast normalization, NHWC (16,1024,1024,2) fp32.
//
// Warp-autonomous design: each warp owns a 64-wide x 64-tall output tile.
// No __syncthreads, no shared memory. Per image row the warp:
//   1) loads the 128-col halo'd strip of the row-difference (enter - leave)
//      as 4 lane-major chunks (coalesced float2 loads),
//   2) warp-scans each chunk (shfl) + carry chain -> row prefix P,
//   3) accumulates VP[x] += P[x]  (vertically integrated prefix, registers),
//   4) extracts 2-D box sums  VP[x+30] - VP[x-31]  via predicated shuffles.
// Stage1: mid = x - box(x)/7442.   Stage2: m=box(mid)/D, q=box(mid^2)/D,
//         res = mid / (sqrt(q - m^2) + 1e-7).

#define NIMG 16
#define HH   1024
#define WW   1024
#define RAD  30
#define FS   61
#define SW   64                  // strip width (outputs per warp per row)
#define SEG  64                  // output rows per warp
#define NSTRIP (WW / SW)         // 16
#define NSEGV  (HH / SEG)        // 16
#define WPB  8                   // warps per block
#define NBLK ((NIMG * NSTRIP * NSEGV) / WPB)   // 512
#define INV_D (1.0f / 7442.0f)   // 1/(61*61*2), denom includes C per reference
#define EPS  1e-7f

__device__ float2 g_mid[(size_t)NIMG * HH * WW];   // 128MB scratch (no alloc)

__device__ __forceinline__ float2 shfl2(float2 v, int src) {
    float2 r;
    r.x = __shfl_sync(0xffffffffu, v.x, src);
    r.y = __shfl_sync(0xffffffffu, v.y, src);
    return r;
}

__device__ __forceinline__ void wscan2(float2& v, int lane) {
#pragma unroll
    for (int off = 1; off < 32; off <<= 1) {
        float ax = __shfl_up_sync(0xffffffffu, v.x, off);
        float ay = __shfl_up_sync(0xffffffffu, v.y, off);
        if (lane >= off) { v.x += ax; v.y += ay; }
    }
}

template<bool S2>
__global__ __launch_bounds__(WPB * 32, 3)
void lcn_kernel(const float2* __restrict__ in, float2* __restrict__ out)
{
    const int lane = threadIdx.x & 31;
    const int unit = blockIdx.x * WPB + (threadIdx.x >> 5);

    const int img   = unit >> 8;          // 16 strips * 16 segs = 256 per image
    const int rem   = unit & 255;
    const int strip = rem & 15;
    const int seg   = rem >> 4;

    const int gx0  = strip * SW;
    const int ys0  = seg * SEG;
    const int base = gx0 - 32;

    const float2* __restrict__ src = in  + (size_t)img * HH * WW;
    float2*       __restrict__ dst = out + (size_t)img * HH * WW;

    // lane-major chunk columns + validity
    int  col[4];
    bool cok[4];
#pragma unroll
    for (int c = 0; c < 4; ++c) {
        col[c] = base + (c << 5) + lane;
        cok[c] = (unsigned)col[c] < (unsigned)WW;
    }

    float2 Va[4], Vb[4];
#pragma unroll
    for (int c = 0; c < 4; ++c) {
        Va[c] = make_float2(0.f, 0.f);
        if (S2) Vb[c] = make_float2(0.f, 0.f);
    }

    const float2 Z = make_float2(0.f, 0.f);

    // ---- priming: accumulate rows ys0-31 .. ys0+29 (no leave) ----
    for (int it = 0; it < FS; ++it) {
        const int r = ys0 - 31 + it;
        if (r < 0) continue;
        const float2* rp = src + (size_t)r * WW;

        float2 d[4], d2[4];
#pragma unroll
        for (int c = 0; c < 4; ++c) {
            float2 e = cok[c] ? __ldg(rp + col[c]) : Z;
            d[c] = e;
            if (S2) d2[c] = make_float2(e.x * e.x, e.y * e.y);
        }
#pragma unroll
        for (int c = 0; c < 4; ++c) { wscan2(d[c], lane); if (S2) wscan2(d2[c], lane); }
        float2 ca = Z, cb = Z;
#pragma unroll
        for (int c = 0; c < 4; ++c) {
            float2 ta = shfl2(d[c], 31);
            Va[c].x += d[c].x + ca.x;  Va[c].y += d[c].y + ca.y;
            ca.x += ta.x;  ca.y += ta.y;
            if (S2) {
                float2 tb = shfl2(d2[c], 31);
                Vb[c].x += d2[c].x + cb.x;  Vb[c].y += d2[c].y + cb.y;
                cb.x += tb.x;  cb.y += tb.y;
            }
        }
    }

    // extraction helpers (warp-uniform per lane)
    const int  idx_hi  = (lane < 2)  ? lane + 30 : lane - 2;   // j = 62+l (rel)
    const bool pick_hi = (lane >= 2);
    const int  idx_lo  = (lane < 31) ? lane + 1  : 0;          // j = 1+l
    const bool pick_lo = (lane == 31);

    const int oc1 = gx0 + lane;        // output cols owned by this lane
    const int oc2 = gx0 + 32 + lane;

    // ---- emit loop: rows ys0 .. ys0+63 ----
    for (int k = 0; k < SEG; ++k) {
        const int yc    = ys0 + k;
        const int enter = yc + RAD;
        const int leave = yc - RAD - 1;
        const bool eok  = enter < HH;      // enter >= 30 always
        const bool lok  = leave >= 0;

        const float2* ep = src + (size_t)enter * WW;
        const float2* lp = src + (size_t)leave * WW;

        float2 d[4], d2[4];
#pragma unroll
        for (int c = 0; c < 4; ++c) {
            float2 e = (eok && cok[c]) ? __ldg(ep + col[c]) : Z;
            float2 l = (lok && cok[c]) ? __ldg(lp + col[c]) : Z;
            d[c] = make_float2(e.x - l.x, e.y - l.y);
            if (S2) d2[c] = make_float2(e.x * e.x - l.x * l.x,
                                        e.y * e.y - l.y * l.y);
        }
#pragma unroll
        for (int c = 0; c < 4; ++c) { wscan2(d[c], lane); if (S2) wscan2(d2[c], lane); }
        float2 ca = Z, cb = Z;
#pragma unroll
        for (int c = 0; c < 4; ++c) {
            float2 ta = shfl2(d[c], 31);
            Va[c].x += d[c].x + ca.x;  Va[c].y += d[c].y + ca.y;
            ca.x += ta.x;  ca.y += ta.y;
            if (S2) {
                float2 tb = shfl2(d2[c], 31);
                Vb[c].x += d2[c].x + cb.x;  Vb[c].y += d2[c].y + cb.y;
                cb.x += tb.x;  cb.y += tb.y;
            }
        }

        // 2-D box sums: W[o] = VP[o+30] - VP[o-31]
        float2 h1a_a = shfl2(Va[1], idx_hi), h1a_b = shfl2(Va[2], idx_hi);
        float2 l1a_a = shfl2(Va[0], idx_lo), l1a_b = shfl2(Va[1], idx_lo);
        float2 h2a_a = shfl2(Va[2], idx_hi), h2a_b = shfl2(Va[3], idx_hi);
        float2 l2a_a = shfl2(Va[1], idx_lo), l2a_b = shfl2(Va[2], idx_lo);
        float2 h1a = pick_hi ? h1a_b : h1a_a;
        float2 l1a = pick_lo ? l1a_b : l1a_a;
        float2 h2a = pick_hi ? h2a_b : h2a_a;
        float2 l2a = pick_lo ? l2a_b : l2a_a;
        float2 W1a = make_float2(h1a.x - l1a.x, h1a.y - l1a.y);
        float2 W2a = make_float2(h2a.x - l2a.x, h2a.y - l2a.y);

        const float2* cp = src + (size_t)yc * WW;
        float2 c1 = __ldg(cp + oc1);
        float2 c2 = __ldg(cp + oc2);
        float2* op = dst + (size_t)yc * WW;

        if (!S2) {
            op[oc1] = make_float2(c1.x - W1a.x * INV_D, c1.y - W1a.y * INV_D);
            op[oc2] = make_float2(c2.x - W2a.x * INV_D, c2.y - W2a.y * INV_D);
        } else {
            float2 h1b_a = shfl2(Vb[1], idx_hi), h1b_b = shfl2(Vb[2], idx_hi);
            float2 l1b_a = shfl2(Vb[0], idx_lo), l1b_b = shfl2(Vb[1], idx_lo);
            float2 h2b_a = shfl2(Vb[2], idx_hi), h2b_b = shfl2(Vb[3], idx_hi);
            float2 l2b_a = shfl2(Vb[1], idx_lo), l2b_b = shfl2(Vb[2], idx_lo);
            float2 h1b = pick_hi ? h1b_b : h1b_a;
            float2 l1b = pick_lo ? l1b_b : l1b_a;
            float2 h2b = pick_hi ? h2b_b : h2b_a;
            float2 l2b = pick_lo ? l2b_b : l2b_a;
            float2 W1b = make_float2(h1b.x - l1b.x, h1b.y - l1b.y);
            float2 W2b = make_float2(h2b.x - l2b.x, h2b.y - l2b.y);

            float m1x = W1a.x * INV_D, m1y = W1a.y * INV_D;
            float q1x = W1b.x * INV_D, q1y = W1b.y * INV_D;
            float s1x = sqrtf(fmaxf(q1x - m1x * m1x, 0.f)) + EPS;
            float s1y = sqrtf(fmaxf(q1y - m1y * m1y, 0.f)) + EPS;
            op[oc1] = make_float2(__fdividef(c1.x, s1x), __fdividef(c1.y, s1y));

            float m2x = W2a.x * INV_D, m2y = W2a.y * INV_D;
            float q2x = W2b.x * INV_D, q2y = W2b.y * INV_D;
            float s2x = sqrtf(fmaxf(q2x - m2x * m2x, 0.f)) + EPS;
            float s2y = sqrtf(fmaxf(q2y - m2y * m2y, 0.f)) + EPS;
            op[oc2] = make_float2(__fdividef(c2.x, s2x), __fdividef(c2.y, s2y));
        }
    }
}

extern "C" void kernel_launch(void* const* d_in, const int* in_sizes, int n_in,
                              void* d_out, int out_size)
{
    (void)in_sizes; (void)n_in; (void)out_size;
    const float2* x   = (const float2*)d_in[0];
    float2*       res = (float2*)d_out;

    float2* mid;
    cudaGetSymbolAddress((void**)&mid, g_mid);

    lcn_kernel<false><<<NBLK, WPB * 32>>>(x, mid);
    lcn_kernel<true ><<<NBLK, WPB * 32>>>(mid, res);
}